// round 17
// baseline (speedup 1.0000x reference)
#include <cuda_runtime.h>
#include <math.h>

// Sinkhorn approximate EMD: B=8, N=2048, 3D points, 50 iterations.
// R17: R11 structure (128 CTAs x 1024 thr, 16 CTAs/batch, 128 rows/CTA,
// smem staging + LDS gathers, packed ELL K>=1e-17, prefetch across wait,
// multiplicative updates) with the counting barrier replaced by PER-CTA
// DATAFLOW FLAGS: producer t0 does st.release flag=half+1 after its slice
// is stored; consumer staging warp w polls ONLY flag[w] (ld.acquire) then
// loads that 128-float slice. One-way visibility replaces the two-sided
// barrier; stragglers overlap with staging of finished slices.

#define BB 8
#define NN 2048
#define NROWS (BB * NN)          // 16384
#define RSTRIDE 256              // padded max nnz per row (avg ~41, max ~150)
#define D2CUT 0.391510f          // ln(1e17)/100  -> K >= 1e-17
#define CPB 16                   // CTAs per batch
#define RPC 128                  // rows per CTA
#define TPB 1024                 // 128 groups x 8 lanes

__device__ unsigned g_pk[2][(size_t)NROWS * RSTRIDE];   // packed K / K^T (33.5 MB)
__device__ float    g_expu[NROWS], g_expv[NROWS];
__device__ float    g_part[BB * CPB];
__device__ unsigned g_flag[BB * CPB];   // per-CTA completed-halves epoch (reset at end)
__device__ unsigned g_bar[BB];          // final counting barrier (reset at end)

__device__ __forceinline__ void st_release(unsigned* p, unsigned v) {
    asm volatile("st.release.gpu.u32 [%0], %1;" :: "l"(p), "r"(v) : "memory");
}
__device__ __forceinline__ unsigned ld_acquire(const unsigned* p) {
    unsigned v;
    asm volatile("ld.acquire.gpu.u32 %0, [%1];" : "=r"(v) : "l"(p) : "memory");
    return v;
}
__device__ __forceinline__ void bar_arrive(unsigned* p) {
    asm volatile("red.release.gpu.add.u32 [%0], 1;" :: "l"(p) : "memory");
}

__device__ __forceinline__ float dot4(uint4 e, const float* sev) {
    return __uint_as_float(e.x & 0xFFFFF800u) * sev[e.x & 0x7FFu]
         + __uint_as_float(e.y & 0xFFFFF800u) * sev[e.y & 0x7FFu]
         + __uint_as_float(e.z & 0xFFFFF800u) * sev[e.z & 0x7FFu]
         + __uint_as_float(e.w & 0xFFFFF800u) * sev[e.w & 0x7FFu];
}

// ---------------------------------------------------------------------------
__global__ __launch_bounds__(TPB, 1)
void fused_sinkhorn(const float* __restrict__ x1, const float* __restrict__ x2,
                    float* __restrict__ out, float M) {
    __shared__ float sxbuf[NN * 3];          // build staging; first 2048 reused as sev
    __shared__ unsigned char sit[2][RPC];    // per-row 32-entry iteration counts
    __shared__ float red[32];
    float* sev = sxbuf;

    int cta = blockIdx.x, batch = cta >> 4, crank = cta & (CPB - 1);
    int t = threadIdx.x, warp = t >> 5, lane = t & 31;
    int rowbase = batch * NN + crank * RPC;
    unsigned* myflag = &g_flag[batch * CPB + crank];
    const float eps = 1e-8f;

    // ===== inline build: CTA-private packed-ELL rows of K and K^T =====
    #pragma unroll 1
    for (int m = 0; m < 2; ++m) {
        const float* rowpts = m ? x2 : x1;
        const float* colpts = m ? x1 : x2;
        const float* cp = colpts + (size_t)batch * NN * 3;
        for (int i = t; i < NN * 3; i += TPB) sxbuf[i] = cp[i];
        __syncthreads();

        #pragma unroll 1
        for (int rr = 0; rr < 4; ++rr) {             // 4 rows per warp (32 warps)
            int r   = warp * 4 + rr;
            int row = rowbase + r;
            const float* ap = rowpts + (size_t)row * 3;
            float ax = ap[0], ay = ap[1], az = ap[2];
            unsigned* krow = g_pk[m] + (size_t)row * RSTRIDE;

            unsigned base = 0;
            for (int c0 = 0; c0 < NN; c0 += 32) {
                int c = c0 + lane;
                float dx = ax - sxbuf[3 * c];
                float dy = ay - sxbuf[3 * c + 1];
                float dz = az - sxbuf[3 * c + 2];
                float d2 = fmaf(dx, dx, fmaf(dy, dy, dz * dz));
                bool p = d2 < D2CUT;
                unsigned mk = __ballot_sync(0xffffffffu, p);
                if (p) {
                    unsigned idx = base + __popc(mk & ((1u << lane) - 1u));
                    if (idx < RSTRIDE)   // RN-rounded 21-bit val | 11-bit col
                        krow[idx] = ((__float_as_uint(__expf(-100.0f * d2)) + 0x400u)
                                     & 0xFFFFF800u) | (unsigned)c;
                }
                base += __popc(mk);
            }
            unsigned nnz = (base < RSTRIDE) ? base : RSTRIDE;
            unsigned pad = (nnz + 31u) & ~31u;       // 32 entries per group-iter
            for (unsigned idx = nnz + lane; idx < pad; idx += 32) krow[idx] = 0u;
            if (lane == 0) sit[m][r] = (unsigned char)(pad >> 5);
        }
        __syncthreads();
    }

    // ===== 100 Sinkhorn half-iterations (dataflow-flag synchronized) =====
    int g = t >> 3, gl = t & 7;                      // 128 groups x 8 lanes
    int myrow = rowbase + g;
    int itc0 = sit[0][g], itc1 = sit[1][g];
    const uint4* ep0 = (const uint4*)(g_pk[0] + (size_t)myrow * RSTRIDE) + gl;
    const uint4* ep1 = (const uint4*)(g_pk[1] + (size_t)myrow * RSTRIDE) + gl;
    float myeu = 0.0f;                               // leader: final exp(u)

    // prefetch half 0's first 64 entries (in-bounds: 8 uint4 per lane)
    uint4 f0 = ep0[0];
    uint4 f1 = ep0[8];

    #pragma unroll 1
    for (int half = 0; half < 100; ++half) {
        int m = half & 1;   // 0: u update (K, reads expv); 1: v update (K^T, reads expu)

        // stage: warp w waits ONLY for producer CTA w's slice, then loads it
        if (warp < CPB) {
            if (half == 0) {
                ((float4*)sev)[t] = make_float4(1.f, 1.f, 1.f, 1.f);  // exp(v0)=1
            } else {
                const unsigned* fp = &g_flag[batch * CPB + warp];
                while (ld_acquire(fp) < (unsigned)half) { }
                ((float4*)sev)[t] =
                    __ldcg((const float4*)((m ? g_expu : g_expv) + batch * NN) + t);
            }
        }
        __syncthreads();

        int iters = m ? itc1 : itc0;
        const uint4* ep = m ? ep1 : ep0;

        float acc = dot4(f0, sev);                   // prefetched chunks
        if (iters > 1) acc += dot4(f1, sev);
        #pragma unroll 1
        for (int i = 2; i < iters; ++i)              // rare tail (nnz > 64)
            acc += dot4(ep[(size_t)i * 8], sev);

        acc += __shfl_xor_sync(0xffffffffu, acc, 4);
        acc += __shfl_xor_sync(0xffffffffu, acc, 2);
        acc += __shfl_xor_sync(0xffffffffu, acc, 1);

        if (gl == 0) {       // multiplicative update: exp(new) = M / (sum + eps)
            float ev = __fdividef(M, acc + eps);
            if (m == 0) myeu = ev;                   // half 98 leaves final exp(u)
            __stcg((m ? g_expv : g_expu) + myrow, ev);
        }

        // prefetch NEXT half's first 64 entries (matrix constant — no dependency)
        {
            const uint4* nep = m ? ep0 : ep1;
            f0 = nep[0];
            f1 = nep[8];
        }
        __syncthreads();                             // slice stores complete CTA-wide
        if (t == 0) st_release(myflag, (unsigned)(half + 1));   // publish epoch
    }

    // ===== epilogue: emd_b = -(1/100) sum_ij k ln(k) e^{u_i} e^{v_j} =====
    if (warp < CPB) {      // wait for all producers' half-99 (epoch 100), stage expv
        const unsigned* fp = &g_flag[batch * CPB + warp];
        while (ld_acquire(fp) < 100u) { }
        ((float4*)sev)[t] = __ldcg((const float4*)(g_expv + batch * NN) + t);
    }
    __syncthreads();

    float racc = 0.0f;
    #pragma unroll 1
    for (int i = 0; i < itc0; ++i) {
        uint4 e = ep0[(size_t)i * 8];
        unsigned b;
        b = e.x & 0xFFFFF800u;
        if (b) { float k = __uint_as_float(b); racc += k * __logf(k) * sev[e.x & 0x7FFu]; }
        b = e.y & 0xFFFFF800u;
        if (b) { float k = __uint_as_float(b); racc += k * __logf(k) * sev[e.y & 0x7FFu]; }
        b = e.z & 0xFFFFF800u;
        if (b) { float k = __uint_as_float(b); racc += k * __logf(k) * sev[e.z & 0x7FFu]; }
        b = e.w & 0xFFFFF800u;
        if (b) { float k = __uint_as_float(b); racc += k * __logf(k) * sev[e.w & 0x7FFu]; }
    }
    racc += __shfl_xor_sync(0xffffffffu, racc, 4);
    racc += __shfl_xor_sync(0xffffffffu, racc, 2);
    racc += __shfl_xor_sync(0xffffffffu, racc, 1);

    float acc = (gl == 0) ? racc * myeu : 0.0f;      // leaders carry row sums
    #pragma unroll
    for (int o = 16; o; o >>= 1) acc += __shfl_down_sync(0xffffffffu, acc, o);
    if (lane == 0) red[warp] = acc;
    __syncthreads();
    if (warp == 0) {
        float s = red[lane];
        #pragma unroll
        for (int o = 16; o; o >>= 1) s += __shfl_down_sync(0xffffffffu, s, o);
        if (lane == 0) __stcg(&g_part[cta], s);
    }
    __syncthreads();

    // final counting barrier: partials ready; crank 0 reduces, resets state
    if (t == 0) {
        bar_arrive(&g_bar[batch]);                   // release covers g_part store
        if (crank == 0) {
            while (ld_acquire(&g_bar[batch]) < (unsigned)CPB) { }
            float s = 0.0f;
            #pragma unroll
            for (int k = 0; k < CPB; ++k) s += __ldcg(&g_part[batch * CPB + k]);
            out[batch] = -s * 0.01f;                 // cost = -ln(K)/100
            g_bar[batch] = 0u;                       // reset for next graph replay
            #pragma unroll
            for (int k = 0; k < CPB; ++k) g_flag[batch * CPB + k] = 0u;
        }
    }
}

// ---------------------------------------------------------------------------
extern "C" void kernel_launch(void* const* d_in, const int* in_sizes, int n_in,
                              void* d_out, int out_size) {
    (void)in_sizes; (void)n_in; (void)out_size;
    const float* x1 = (const float*)d_in[0];
    const float* x2 = (const float*)d_in[1];
    float* out = (float*)d_out;

    const float M = 1.0f / 2048.0f + 1e-8f;   // exp(log(1/N + eps_log))
    fused_sinkhorn<<<BB * CPB, TPB>>>(x1, x2, out, M);
}